// round 10
// baseline (speedup 1.0000x reference)
#include <cuda_runtime.h>
#include <cuda_fp16.h>
#include <math.h>
#include <stdint.h>

// ---------------- problem dims ----------------
#define B_      2
#define S_      2048
#define DM      2048
#define NH      16
#define DNOPE   128
#define DROPE   64
#define DQKD    192
#define DKVL    512
#define DV      128
#define BS      (B_*S_)          // 4096
#define HQ      (NH*DQKD)        // 3072
#define HKV     (NH*(DNOPE+DV))  // 4096
#define KVA_N   (DKVL+DROPE)     // 576
#define QKVA_N  (HQ+KVA_N)       // 3648 (merged q + kva projection)
#define RMS_EPS 1.1920928955078125e-07f
#define ROPE_LC 0.28782313662425572f   // ln(10000)/32

// ---------------- scratch (fp16 pipeline) ----------------
__device__ alignas(16) __half g_qkvah[BS*QKVA_N];  // [q (3072) | kva (576)]
__device__ alignas(16) __half g_ckvh[BS*DKVL];
__device__ alignas(16) __half g_krh [BS*DROPE];
__device__ alignas(16) __half g_kvbh[BS*HKV];
__device__ alignas(16) __half g_atth[BS*(NH*DV)];
__device__ alignas(16) __half g_xh  [BS*DM];
__device__ alignas(16) __half g_wqaTh[QKVA_N*DM];  // [WqT | WkvaT] k-major
__device__ alignas(16) __half g_wkvbTh[HKV*DKVL];
__device__ alignas(16) __half g_woTh [DM*NH*DV];

// ---------------- helpers ----------------
__device__ __forceinline__ void mma16(float* c, const unsigned* a,
                                      unsigned b0, unsigned b1) {
    asm volatile(
        "mma.sync.aligned.m16n8k16.row.col.f32.f16.f16.f32 "
        "{%0,%1,%2,%3},{%4,%5,%6,%7},{%8,%9},{%0,%1,%2,%3};\n"
        : "+f"(c[0]), "+f"(c[1]), "+f"(c[2]), "+f"(c[3])
        : "r"(a[0]), "r"(a[1]), "r"(a[2]), "r"(a[3]), "r"(b0), "r"(b1));
}

__device__ __forceinline__ void ldsm4(unsigned* r, uint32_t addr) {
    asm volatile("ldmatrix.sync.aligned.m8n8.x4.shared.b16 {%0,%1,%2,%3}, [%4];"
                 : "=r"(r[0]), "=r"(r[1]), "=r"(r[2]), "=r"(r[3]) : "r"(addr));
}
__device__ __forceinline__ void ldsm4t(unsigned* r, uint32_t addr) {
    asm volatile("ldmatrix.sync.aligned.m8n8.x4.trans.shared.b16 {%0,%1,%2,%3}, [%4];"
                 : "=r"(r[0]), "=r"(r[1]), "=r"(r[2]), "=r"(r[3]) : "r"(addr));
}

__device__ __forceinline__ void cp_async16(uint32_t dst, const void* src, int srcBytes) {
    asm volatile("cp.async.cg.shared.global [%0], [%1], 16, %2;\n"
                 :: "r"(dst), "l"(src), "r"(srcBytes));
}
#define CP_COMMIT() asm volatile("cp.async.commit_group;\n" ::: "memory")
#define CP_WAIT(n)  asm volatile("cp.async.wait_group %0;\n" :: "n"(n) : "memory")

__device__ __forceinline__ unsigned packh2(float a, float b) {
    const __half2 h = __floats2half2_rn(a, b);
    return *(const unsigned*)&h;
}

// ---------------- fp32 -> fp16 conversion passes ----------------
__global__ void f2h_kernel(const float4* __restrict__ in,
                           __half2* __restrict__ out, int n4)
{
    const int i = blockIdx.x * blockDim.x + threadIdx.x;
    if (i < n4) {
        const float4 v = in[i];
        out[2 * i]     = __floats2half2_rn(v.x, v.y);
        out[2 * i + 1] = __floats2half2_rn(v.z, v.w);
    }
}

// in[R][C] fp32 -> out[C][R] fp16. R,C % 32 == 0. block (32,8).
__global__ void trTh_kernel(const float* __restrict__ in, __half* __restrict__ out,
                            int R, int Cc)
{
    __shared__ float t[32][33];
    const int c0 = blockIdx.x * 32, r0 = blockIdx.y * 32;
    const int tx = threadIdx.x, ty = threadIdx.y;
#pragma unroll
    for (int i = 0; i < 4; i++)
        t[ty + i * 8][tx] = in[(size_t)(r0 + ty + i * 8) * Cc + c0 + tx];
    __syncthreads();
#pragma unroll
    for (int i = 0; i < 4; i++)
        out[(size_t)(c0 + ty + i * 8) * R + r0 + tx] = __float2half_rn(t[tx][ty + i * 8]);
}

// ---------------- fp16 GEMM: C[M,N] = A[M,K] @ Bt[N,K]^T --------------------
// 128x256x64 tile, 256 thr (8 warps: wm 0..1 x wn 0..3), warp 64x64.
// 2-stage cp.async, 110.6KB smem (1 CTA/SM by regs). M%128==0, K%64==0, N guarded.
#define GASTRH   72
#define GA_BYTES (128 * GASTRH * 2)     // 18432
#define GB_BYTES (256 * GASTRH * 2)     // 36864
#define GSTAGE_B (GA_BYTES + GB_BYTES)  // 55296
#define GEMM_SMEM_BYTES (2 * GSTAGE_B)  // 110592

__global__ void __launch_bounds__(256)
gemm_h(const __half* __restrict__ A, const __half* __restrict__ Bt,
       void* __restrict__ C, int M, int N, int K, int outHalf)
{
    extern __shared__ __half hsm[];
    const uint32_t sb = (uint32_t)__cvta_generic_to_shared(hsm);

    const int tid  = threadIdx.x;
    const int wid  = tid >> 5;
    const int lane = tid & 31;
    const int lr   = lane >> 2;
    const int lc   = lane & 3;
    const int g    = lane >> 3;
    const int l8   = lane & 7;
    const int wm   = wid & 1;       // 0..1 -> 64-row strip
    const int wn   = wid >> 1;      // 0..3 -> 64-col strip
    const int m0   = blockIdx.y * 128;
    const int n0   = blockIdx.x * 256;

    const uint32_t aBase = sb + (((wm * 64 + l8 + 8 * (g & 1)) * GASTRH + 8 * (g >> 1)) << 1);
    const uint32_t bBase = sb + GA_BYTES +
                           (((wn * 64 + l8 + 8 * (g >> 1)) * GASTRH + 8 * (g & 1)) << 1);

    float acc[4][8][4];
#pragma unroll
    for (int i = 0; i < 4; i++)
#pragma unroll
        for (int j = 0; j < 8; j++)
#pragma unroll
            for (int k = 0; k < 4; k++) acc[i][j][k] = 0.f;

    auto loadTile = [&](int stage, int kt) {
        const uint32_t s0 = sb + (uint32_t)stage * GSTAGE_B;
        const int kb = kt * 64;
#pragma unroll
        for (int i = 0; i < 4; i++) {           // A: 128 rows x 8 chunks
            const int idx = tid + i * 256;
            const int row = idx >> 3, c8 = idx & 7;
            cp_async16(s0 + ((row * GASTRH + c8 * 8) << 1),
                       A + (size_t)(m0 + row) * K + kb + c8 * 8, 16);
        }
#pragma unroll
        for (int i = 0; i < 8; i++) {           // B: 256 rows x 8 chunks
            const int idx = tid + i * 256;
            const int n = idx >> 3, c8 = idx & 7;
            const int ng = n0 + n;
            const int ngc = ng < N ? ng : 0;
            cp_async16(s0 + GA_BYTES + ((n * GASTRH + c8 * 8) << 1),
                       Bt + (size_t)ngc * K + kb + c8 * 8, ng < N ? 16 : 0);
        }
        CP_COMMIT();
    };

    const int T = K >> 6;
    loadTile(0, 0);
    if (T > 1) loadTile(1, 1);

    for (int it = 0; it < T; it++) {
        if (it + 1 < T) { CP_WAIT(1); } else { CP_WAIT(0); }
        __syncthreads();

        const uint32_t st = (uint32_t)(it & 1) * GSTAGE_B;
#pragma unroll
        for (int ks = 0; ks < 4; ks++) {
            unsigned a[4][4];
#pragma unroll
            for (int mt = 0; mt < 4; mt++)
                ldsm4(a[mt], aBase + st + ks * 32 + mt * (16 * GASTRH * 2));
            unsigned b[8][2];
#pragma unroll
            for (int p = 0; p < 4; p++) {
                unsigned bb[4];
                ldsm4(bb, bBase + st + ks * 32 + p * (16 * GASTRH * 2));
                b[2 * p][0] = bb[0]; b[2 * p][1] = bb[1];
                b[2 * p + 1][0] = bb[2]; b[2 * p + 1][1] = bb[3];
            }
#pragma unroll
            for (int mt = 0; mt < 4; mt++)
#pragma unroll
                for (int nt = 0; nt < 8; nt++)
                    mma16(acc[mt][nt], a[mt], b[nt][0], b[nt][1]);
        }
        if (it + 2 < T) {
            __syncthreads();
            loadTile(it & 1, it + 2);
        }
    }

#pragma unroll
    for (int mt = 0; mt < 4; mt++)
#pragma unroll
        for (int nt = 0; nt < 8; nt++) {
            const int row = m0 + wm * 64 + mt * 16 + lr;
            const int col = n0 + wn * 64 + nt * 8 + 2 * lc;
            if (col < N) {
                if (outHalf) {
                    *(__half2*)((__half*)C + (size_t)row * N + col) =
                        __floats2half2_rn(acc[mt][nt][0], acc[mt][nt][1]);
                    *(__half2*)((__half*)C + (size_t)(row + 8) * N + col) =
                        __floats2half2_rn(acc[mt][nt][2], acc[mt][nt][3]);
                } else {
                    *(float2*)((float*)C + (size_t)row * N + col) =
                        make_float2(acc[mt][nt][0], acc[mt][nt][1]);
                    *(float2*)((float*)C + (size_t)(row + 8) * N + col) =
                        make_float2(acc[mt][nt][2], acc[mt][nt][3]);
                }
            }
        }
}

// ---------------- prep: RMSNorm(c_kv), RoPE(k_rope), RoPE(q) -----------------
// kva lives at column offset HQ of the merged projection buffer.
__global__ void prep_kernel(const float* __restrict__ w)
{
    const int row = blockIdx.x;
    const int s   = row % S_;
    const int tid = threadIdx.x;
    const __half* kva = g_qkvah + (size_t)row * QKVA_N + HQ;

    const float c0 = __half2float(kva[tid]);
    const float c1 = __half2float(kva[tid + 256]);
    float ss = c0 * c0 + c1 * c1;
#pragma unroll
    for (int o = 16; o > 0; o >>= 1) ss += __shfl_xor_sync(0xffffffffu, ss, o);
    __shared__ float red[8];
    if ((tid & 31) == 0) red[tid >> 5] = ss;
    __syncthreads();
    if (tid == 0) {
        float v = 0.f;
#pragma unroll
        for (int i = 0; i < 8; i++) v += red[i];
        red[0] = v;
    }
    __syncthreads();
    const float inv = rsqrtf(red[0] * (1.f / 512.f) + RMS_EPS);
    g_ckvh[(size_t)row * DKVL + tid]       = __float2half_rn(c0 * inv * w[tid]);
    g_ckvh[(size_t)row * DKVL + tid + 256] = __float2half_rn(c1 * inv * w[tid + 256]);

    if (tid < 32) {
        const float fr = expf(-(float)tid * ROPE_LC);
        const float t  = (float)s * fr;
        const float cs = cosf(t), sn = sinf(t);
        const float x1 = __half2float(kva[DKVL + 2 * tid]);
        const float x2 = __half2float(kva[DKVL + 2 * tid + 1]);
        *(__half2*)(g_krh + (size_t)row * DROPE + 2 * tid) =
            __floats2half2_rn(x1 * cs - x2 * sn, x2 * cs + x1 * sn);
    }

    for (int p = tid; p < NH * 32; p += 256) {
        const int h = p >> 5, i = p & 31;
        const float fr = expf(-(float)i * ROPE_LC);
        const float t  = (float)s * fr;
        const float cs = cosf(t), sn = sinf(t);
        __half2* qp = (__half2*)(g_qkvah + (size_t)row * QKVA_N + h * DQKD + DNOPE + 2 * i);
        const __half2 v = *qp;
        const float x1 = __half2float(v.x), x2 = __half2float(v.y);
        *qp = __floats2half2_rn(x1 * cs - x2 * sn, x2 * cs + x1 * sn);
    }
}

// ---------------- fp16 tensor-core flash attention (BM=128, BN=64) -----------
// P stays in registers (C-frag == A-frag layout after half2 packing).
#define QS_STRH 200
#define KS_STRH 200
#define VS_STRH 136

#define QS_OFFH 0
#define KS_OFFH (128 * QS_STRH)            // 25600
#define VS_OFFH (KS_OFFH + 64 * KS_STRH)   // 38400
#define ATT_HALVES (VS_OFFH + 64 * VS_STRH)
#define ATT_BYTES (ATT_HALVES * 2)         // 94208

__global__ void __launch_bounds__(256, 2)
attn_tc()
{
    extern __shared__ __half asm_[];
    const uint32_t sbase = (uint32_t)__cvta_generic_to_shared(asm_);
    const uint32_t sQ = sbase;
    const uint32_t sK = sbase + KS_OFFH * 2;
    const uint32_t sV = sbase + VS_OFFH * 2;

    // LPT scheduling: longest CTAs (largest qblk) launch first
    const int qblk = (S_ / 128 - 1) - blockIdx.x;
    const int h    = blockIdx.y;
    const int b    = blockIdx.z;
    const int tid  = threadIdx.x;
    const int w    = tid >> 5;
    const int lane = tid & 31;
    const int lr   = lane >> 2;
    const int lc   = lane & 3;
    const int g    = lane >> 3;
    const int l8   = lane & 7;
    const int w16  = w * 16;
    const int q0   = qblk * 128;
    const int bS   = b * S_;

    // scale * log2(e): softmax runs in log2 domain, exp2f = single MUFU
    const float scale2 = 0.07216878364870323f * 1.4426950408889634f;

    const uint32_t qB = sQ + (((w16 + l8 + 8 * (g & 1)) * QS_STRH + 8 * (g >> 1)) << 1);
    const uint32_t kB = sK + (((l8 + 8 * (g >> 1)) * KS_STRH + 8 * (g & 1)) << 1);
    const uint32_t vB = sV + (((l8 + 8 * (g & 1)) * VS_STRH + 8 * (g >> 1)) << 1);

#pragma unroll
    for (int i = 0; i < 12; i++) {
        const int idx = tid + i * 256;
        const int r = idx / 24, c8 = idx % 24;
        cp_async16(sQ + ((r * QS_STRH + c8 * 8) << 1),
                   g_qkvah + (size_t)(bS + q0 + r) * QKVA_N + h * DQKD + c8 * 8, 16);
    }
    CP_COMMIT();

    float oacc[16][4];
#pragma unroll
    for (int i = 0; i < 16; i++)
#pragma unroll
        for (int j = 0; j < 4; j++) oacc[i][j] = 0.f;
    float m0v = -1e30f, m1v = -1e30f, l0 = 0.f, l1 = 0.f;

    const int row0g = q0 + w16 + lr;
    const int row1g = row0g + 8;
    const int lastNeeded = q0 + w16 + 15;

    CP_WAIT(0);
    __syncthreads();

    const int ktMax = 2 * qblk + 1;
    for (int kt = 0; kt <= ktMax; kt++) {
        const int k0 = kt * 64;

#pragma unroll
        for (int i = 0; i < 4; i++) {
            const int idx = tid + i * 256;
            const int j = idx >> 4, c8 = idx & 15;
            cp_async16(sK + ((j * KS_STRH + c8 * 8) << 1),
                       g_kvbh + (size_t)(bS + k0 + j) * HKV + h * 256 + c8 * 8, 16);
        }
#pragma unroll
        for (int i = 0; i < 2; i++) {
            const int idx = tid + i * 256;
            const int j = idx >> 3, c8 = idx & 7;
            cp_async16(sK + ((j * KS_STRH + 128 + c8 * 8) << 1),
                       g_krh + (size_t)(bS + k0 + j) * DROPE + c8 * 8, 16);
        }
#pragma unroll
        for (int i = 0; i < 4; i++) {
            const int idx = tid + i * 256;
            const int j = idx >> 4, c8 = idx & 15;
            cp_async16(sV + ((j * VS_STRH + c8 * 8) << 1),
                       g_kvbh + (size_t)(bS + k0 + j) * HKV + h * 256 + 128 + c8 * 8, 16);
        }
        CP_COMMIT();
        CP_WAIT(0);
        __syncthreads();

        if (k0 <= lastNeeded) {
            // ---- S = Q @ K^T ----
            float sacc[8][4];
#pragma unroll
            for (int i = 0; i < 8; i++)
#pragma unroll
                for (int j = 0; j < 4; j++) sacc[i][j] = 0.f;

#pragma unroll
            for (int ks = 0; ks < 12; ks++) {
                unsigned a[4];
                ldsm4(a, qB + ks * 32);
#pragma unroll
                for (int p = 0; p < 4; p++) {
                    unsigned bb[4];
                    ldsm4(bb, kB + ks * 32 + p * (16 * KS_STRH * 2));
                    mma16(sacc[2 * p],     a, bb[0], bb[1]);
                    mma16(sacc[2 * p + 1], a, bb[2], bb[3]);
                }
            }

            // ---- mask + scale (log2 domain), row max ----
            const bool domask = (k0 + 63 > q0 + w16);
            float mt0 = -1e30f, mt1 = -1e30f;
#pragma unroll
            for (int nt = 0; nt < 8; nt++) {
                const int jb = k0 + nt * 8 + 2 * lc;
#pragma unroll
                for (int c = 0; c < 4; c++) {
                    float s = sacc[nt][c] * scale2;
                    const int jg = jb + (c & 1);
                    const int rg = (c < 2) ? row0g : row1g;
                    if (domask && jg > rg) s = -1e30f;
                    sacc[nt][c] = s;
                    if (c < 2) mt0 = fmaxf(mt0, s); else mt1 = fmaxf(mt1, s);
                }
            }
            mt0 = fmaxf(mt0, __shfl_xor_sync(0xffffffffu, mt0, 1));
            mt0 = fmaxf(mt0, __shfl_xor_sync(0xffffffffu, mt0, 2));
            mt1 = fmaxf(mt1, __shfl_xor_sync(0xffffffffu, mt1, 1));
            mt1 = fmaxf(mt1, __shfl_xor_sync(0xffffffffu, mt1, 2));

            const float mn0 = fmaxf(m0v, mt0);
            const float mn1 = fmaxf(m1v, mt1);
            const float al0 = exp2f(m0v - mn0);
            const float al1 = exp2f(m1v - mn1);
            m0v = mn0; m1v = mn1;

            // ---- P = exp2(S - m) in registers; row sums ----
            float rs0 = 0.f, rs1 = 0.f;
#pragma unroll
            for (int nt = 0; nt < 8; nt++) {
                sacc[nt][0] = exp2f(sacc[nt][0] - mn0);
                sacc[nt][1] = exp2f(sacc[nt][1] - mn0);
                sacc[nt][2] = exp2f(sacc[nt][2] - mn1);
                sacc[nt][3] = exp2f(sacc[nt][3] - mn1);
                rs0 += sacc[nt][0] + sacc[nt][1];
                rs1 += sacc[nt][2] + sacc[nt][3];
            }
            rs0 += __shfl_xor_sync(0xffffffffu, rs0, 1);
            rs0 += __shfl_xor_sync(0xffffffffu, rs0, 2);
            rs1 += __shfl_xor_sync(0xffffffffu, rs1, 1);
            rs1 += __shfl_xor_sync(0xffffffffu, rs1, 2);
            l0 = l0 * al0 + rs0;
            l1 = l1 * al1 + rs1;

            // ---- rescale O ----
#pragma unroll
            for (int nt = 0; nt < 16; nt++) {
                oacc[nt][0] *= al0; oacc[nt][1] *= al0;
                oacc[nt][2] *= al1; oacc[nt][3] *= al1;
            }

            // ---- pack P C-frags directly into A-frags (no smem round trip) ----
            unsigned pa[4][4];
#pragma unroll
            for (int ks = 0; ks < 4; ks++) {
                pa[ks][0] = packh2(sacc[2 * ks][0],     sacc[2 * ks][1]);
                pa[ks][1] = packh2(sacc[2 * ks][2],     sacc[2 * ks][3]);
                pa[ks][2] = packh2(sacc[2 * ks + 1][0], sacc[2 * ks + 1][1]);
                pa[ks][3] = packh2(sacc[2 * ks + 1][2], sacc[2 * ks + 1][3]);
            }

            // ---- O += P @ V : V via ldmatrix.trans ----
#pragma unroll
            for (int ks = 0; ks < 4; ks++) {
#pragma unroll
                for (int p = 0; p < 8; p++) {
                    unsigned bb[4];
                    ldsm4t(bb, vB + ks * (16 * VS_STRH * 2) + p * 32);
                    mma16(oacc[2 * p],     pa[ks], bb[0], bb[1]);
                    mma16(oacc[2 * p + 1], pa[ks], bb[2], bb[3]);
                }
            }
        }
        __syncthreads();
    }

    const float inv0 = 1.f / l0;
    const float inv1 = 1.f / l1;
#pragma unroll
    for (int nt = 0; nt < 16; nt++) {
        const int col = h * DV + nt * 8 + 2 * lc;
        *(__half2*)(g_atth + (size_t)(bS + row0g) * (NH * DV) + col) =
            __floats2half2_rn(oacc[nt][0] * inv0, oacc[nt][1] * inv0);
        *(__half2*)(g_atth + (size_t)(bS + row1g) * (NH * DV) + col) =
            __floats2half2_rn(oacc[nt][2] * inv1, oacc[nt][3] * inv1);
    }
}

// ---------------- launch ----------------
extern "C" void kernel_launch(void* const* d_in, const int* in_sizes, int n_in,
                              void* d_out, int out_size)
{
    const float* x     = (const float*)d_in[0];
    const float* Wq    = (const float*)d_in[1];
    const float* Wkv_a = (const float*)d_in[2];
    const float* knw   = (const float*)d_in[3];
    const float* Wkv_b = (const float*)d_in[4];
    const float* Wo    = (const float*)d_in[5];
    float* out = (float*)d_out;

    static __half *p_qkva, *p_ckvh, *p_kvbh, *p_atth;
    static __half *p_xh, *p_wqa, *p_wkvbTh, *p_woTh;
    static bool init = false;
    if (!init) {
        cudaGetSymbolAddress((void**)&p_qkva,   g_qkvah);
        cudaGetSymbolAddress((void**)&p_ckvh,   g_ckvh);
        cudaGetSymbolAddress((void**)&p_kvbh,   g_kvbh);
        cudaGetSymbolAddress((void**)&p_atth,   g_atth);
        cudaGetSymbolAddress((void**)&p_xh,     g_xh);
        cudaGetSymbolAddress((void**)&p_wqa,    g_wqaTh);
        cudaGetSymbolAddress((void**)&p_wkvbTh, g_wkvbTh);
        cudaGetSymbolAddress((void**)&p_woTh,   g_woTh);
        cudaFuncSetAttribute(attn_tc,
                             cudaFuncAttributeMaxDynamicSharedMemorySize, ATT_BYTES);
        cudaFuncSetAttribute(gemm_h,
                             cudaFuncAttributeMaxDynamicSharedMemorySize, GEMM_SMEM_BYTES);
        init = true;
    }

    {
        const int n4 = BS * DM / 4;
        f2h_kernel<<<(n4 + 255) / 256, 256>>>((const float4*)x, (__half2*)p_xh, n4);
    }
    const dim3 tb(32, 8);
    // merged weight: rows 0..3071 = WqT, rows 3072..3647 = WkvaT (k-major)
    trTh_kernel<<<dim3(HQ / 32, DM / 32), tb>>>(Wq, p_wqa, DM, HQ);
    trTh_kernel<<<dim3(KVA_N / 32, DM / 32), tb>>>(Wkv_a, p_wqa + (size_t)HQ * DM, DM, KVA_N);
    trTh_kernel<<<dim3(HKV / 32, DKVL / 32), tb>>>(Wkv_b, p_wkvbTh, DKVL, HKV);
    trTh_kernel<<<dim3(DM / 32, DM / 32), tb>>>(Wo, p_woTh, DM, DM);

    const dim3 blk(256);
    // merged q+kva projection: [BS, 3648]
    gemm_h<<<dim3((QKVA_N + 255) / 256, BS / 128), blk, GEMM_SMEM_BYTES>>>(
        p_xh, p_wqa, p_qkva, BS, QKVA_N, DM, 1);
    prep_kernel<<<BS, 256>>>(knw);
    gemm_h<<<dim3(HKV / 256, BS / 128), blk, GEMM_SMEM_BYTES>>>(
        p_ckvh, p_wkvbTh, p_kvbh, BS, HKV, DKVL, 1);
    attn_tc<<<dim3(S_ / 128, NH, B_), 256, ATT_BYTES>>>();
    gemm_h<<<dim3(DM / 256, BS / 128), blk, GEMM_SMEM_BYTES>>>(
        p_atth, p_woTh, out, BS, DM, DM, 0);
}

// round 11
// speedup vs baseline: 1.0610x; 1.0610x over previous
#include <cuda_runtime.h>
#include <cuda_fp16.h>
#include <math.h>
#include <stdint.h>

// ---------------- problem dims ----------------
#define B_      2
#define S_      2048
#define DM      2048
#define NH      16
#define DNOPE   128
#define DROPE   64
#define DQKD    192
#define DKVL    512
#define DV      128
#define BS      (B_*S_)          // 4096
#define HQ      (NH*DQKD)        // 3072
#define HKV     (NH*(DNOPE+DV))  // 4096
#define KVA_N   (DKVL+DROPE)     // 576
#define QKVA_N  (HQ+KVA_N)       // 3648
#define RMS_EPS 1.1920928955078125e-07f
#define ROPE_LC 0.28782313662425572f   // ln(10000)/32

// ---------------- scratch (fp16 pipeline) ----------------
__device__ alignas(16) __half g_qkvah[BS*QKVA_N];  // [q (3072) | kva (576)]
__device__ alignas(16) __half g_ckvh[BS*DKVL];
__device__ alignas(16) __half g_krh [BS*DROPE];
__device__ alignas(16) __half g_kvbh[BS*HKV];
__device__ alignas(16) __half g_atth[BS*(NH*DV)];
__device__ alignas(16) __half g_xh  [BS*DM];
__device__ alignas(16) __half g_wqaTh[QKVA_N*DM];  // [WqT | WkvaT] k-major
__device__ alignas(16) __half g_wkvbTh[HKV*DKVL];
__device__ alignas(16) __half g_woTh [DM*NH*DV];

// ---------------- helpers ----------------
__device__ __forceinline__ void mma16(float* c, const unsigned* a,
                                      unsigned b0, unsigned b1) {
    asm volatile(
        "mma.sync.aligned.m16n8k16.row.col.f32.f16.f16.f32 "
        "{%0,%1,%2,%3},{%4,%5,%6,%7},{%8,%9},{%0,%1,%2,%3};\n"
        : "+f"(c[0]), "+f"(c[1]), "+f"(c[2]), "+f"(c[3])
        : "r"(a[0]), "r"(a[1]), "r"(a[2]), "r"(a[3]), "r"(b0), "r"(b1));
}

__device__ __forceinline__ void ldsm4(unsigned* r, uint32_t addr) {
    asm volatile("ldmatrix.sync.aligned.m8n8.x4.shared.b16 {%0,%1,%2,%3}, [%4];"
                 : "=r"(r[0]), "=r"(r[1]), "=r"(r[2]), "=r"(r[3]) : "r"(addr));
}
__device__ __forceinline__ void ldsm4t(unsigned* r, uint32_t addr) {
    asm volatile("ldmatrix.sync.aligned.m8n8.x4.trans.shared.b16 {%0,%1,%2,%3}, [%4];"
                 : "=r"(r[0]), "=r"(r[1]), "=r"(r[2]), "=r"(r[3]) : "r"(addr));
}

__device__ __forceinline__ void cp_async16(uint32_t dst, const void* src, int srcBytes) {
    asm volatile("cp.async.cg.shared.global [%0], [%1], 16, %2;\n"
                 :: "r"(dst), "l"(src), "r"(srcBytes));
}
#define CP_COMMIT() asm volatile("cp.async.commit_group;\n" ::: "memory")
#define CP_WAIT(n)  asm volatile("cp.async.wait_group %0;\n" :: "n"(n) : "memory")

__device__ __forceinline__ unsigned packh2(float a, float b) {
    const __half2 h = __floats2half2_rn(a, b);
    return *(const unsigned*)&h;
}

// ---------------- fp32 -> fp16 conversion passes ----------------
__global__ void f2h_kernel(const float4* __restrict__ in,
                           __half2* __restrict__ out, int n4)
{
    const int i = blockIdx.x * blockDim.x + threadIdx.x;
    if (i < n4) {
        const float4 v = in[i];
        out[2 * i]     = __floats2half2_rn(v.x, v.y);
        out[2 * i + 1] = __floats2half2_rn(v.z, v.w);
    }
}

// in[R][C] fp32 -> out[C][R] fp16. R,C % 32 == 0. block (32,8).
__global__ void trTh_kernel(const float* __restrict__ in, __half* __restrict__ out,
                            int R, int Cc)
{
    __shared__ float t[32][33];
    const int c0 = blockIdx.x * 32, r0 = blockIdx.y * 32;
    const int tx = threadIdx.x, ty = threadIdx.y;
#pragma unroll
    for (int i = 0; i < 4; i++)
        t[ty + i * 8][tx] = in[(size_t)(r0 + ty + i * 8) * Cc + c0 + tx];
    __syncthreads();
#pragma unroll
    for (int i = 0; i < 4; i++)
        out[(size_t)(c0 + ty + i * 8) * R + r0 + tx] = __float2half_rn(t[tx][ty + i * 8]);
}

// ---------------- fp16 GEMM: C[M,N] = A[M,K] @ Bt[N,K]^T --------------------
// 128x128x64 tile, 256 thr (8 warps: wm 0..3 x wn 0..1), warp 32x64.
// 2-stage cp.async -> 73.7KB smem -> 2 CTAs/SM.
#define GASTRH   72
#define GTILE_B  (128 * GASTRH * 2)     // 18432
#define GSTAGE_B (2 * GTILE_B)
#define GEMM_SMEM_BYTES (2 * GSTAGE_B)  // 73728

__global__ void __launch_bounds__(256, 2)
gemm_h(const __half* __restrict__ A, const __half* __restrict__ Bt,
       void* __restrict__ C, int M, int N, int K, int outHalf)
{
    extern __shared__ __half hsm[];
    const uint32_t sb = (uint32_t)__cvta_generic_to_shared(hsm);

    const int tid  = threadIdx.x;
    const int wid  = tid >> 5;
    const int lane = tid & 31;
    const int lr   = lane >> 2;
    const int lc   = lane & 3;
    const int g    = lane >> 3;
    const int l8   = lane & 7;
    const int wm   = wid & 3;
    const int wn   = wid >> 2;
    const int m0   = blockIdx.y * 128;
    const int n0   = blockIdx.x * 128;

    const uint32_t aBase = sb + (((wm * 32 + l8 + 8 * (g & 1)) * GASTRH + 8 * (g >> 1)) << 1);
    const uint32_t bBase = sb + GTILE_B +
                           (((wn * 64 + l8 + 8 * (g >> 1)) * GASTRH + 8 * (g & 1)) << 1);

    float acc[2][8][4];
#pragma unroll
    for (int i = 0; i < 2; i++)
#pragma unroll
        for (int j = 0; j < 8; j++)
#pragma unroll
            for (int k = 0; k < 4; k++) acc[i][j][k] = 0.f;

    auto loadTile = [&](int stage, int kt) {
        const uint32_t s0 = sb + (uint32_t)stage * GSTAGE_B;
        const int kb = kt * 64;
#pragma unroll
        for (int i = 0; i < 4; i++) {
            const int idx = tid + i * 256;
            const int row = idx >> 3, c8 = idx & 7;
            cp_async16(s0 + ((row * GASTRH + c8 * 8) << 1),
                       A + (size_t)(m0 + row) * K + kb + c8 * 8, 16);
        }
#pragma unroll
        for (int i = 0; i < 4; i++) {
            const int idx = tid + i * 256;
            const int n = idx >> 3, c8 = idx & 7;
            const int ng = n0 + n;
            const int ngc = ng < N ? ng : 0;
            cp_async16(s0 + GTILE_B + ((n * GASTRH + c8 * 8) << 1),
                       Bt + (size_t)ngc * K + kb + c8 * 8, ng < N ? 16 : 0);
        }
        CP_COMMIT();
    };

    const int T = K >> 6;
    loadTile(0, 0);
    if (T > 1) loadTile(1, 1);

    for (int it = 0; it < T; it++) {
        if (it + 1 < T) { CP_WAIT(1); } else { CP_WAIT(0); }
        __syncthreads();

        const uint32_t st = (uint32_t)(it & 1) * GSTAGE_B;
#pragma unroll
        for (int ks = 0; ks < 4; ks++) {
            unsigned a[2][4];
            ldsm4(a[0], aBase + st + ks * 32);
            ldsm4(a[1], aBase + st + ks * 32 + 16 * GASTRH * 2);
            unsigned b[8][2];
#pragma unroll
            for (int p = 0; p < 4; p++) {
                unsigned bb[4];
                ldsm4(bb, bBase + st + ks * 32 + p * (16 * GASTRH * 2));
                b[2 * p][0] = bb[0]; b[2 * p][1] = bb[1];
                b[2 * p + 1][0] = bb[2]; b[2 * p + 1][1] = bb[3];
            }
#pragma unroll
            for (int nt = 0; nt < 8; nt++) {
                mma16(acc[0][nt], a[0], b[nt][0], b[nt][1]);
                mma16(acc[1][nt], a[1], b[nt][0], b[nt][1]);
            }
        }
        if (it + 2 < T) {
            __syncthreads();
            loadTile(it & 1, it + 2);
        }
    }

#pragma unroll
    for (int mt = 0; mt < 2; mt++)
#pragma unroll
        for (int nt = 0; nt < 8; nt++) {
            const int row = m0 + wm * 32 + mt * 16 + lr;
            const int col = n0 + wn * 64 + nt * 8 + 2 * lc;
            if (col < N) {
                if (outHalf) {
                    *(__half2*)((__half*)C + (size_t)row * N + col) =
                        __floats2half2_rn(acc[mt][nt][0], acc[mt][nt][1]);
                    *(__half2*)((__half*)C + (size_t)(row + 8) * N + col) =
                        __floats2half2_rn(acc[mt][nt][2], acc[mt][nt][3]);
                } else {
                    *(float2*)((float*)C + (size_t)row * N + col) =
                        make_float2(acc[mt][nt][0], acc[mt][nt][1]);
                    *(float2*)((float*)C + (size_t)(row + 8) * N + col) =
                        make_float2(acc[mt][nt][2], acc[mt][nt][3]);
                }
            }
        }
}

// ---------------- prep: RMSNorm(c_kv), RoPE(k_rope), RoPE(q) -----------------
__global__ void prep_kernel(const float* __restrict__ w)
{
    const int row = blockIdx.x;
    const int s   = row % S_;
    const int tid = threadIdx.x;
    const __half* kva = g_qkvah + (size_t)row * QKVA_N + HQ;

    const float c0 = __half2float(kva[tid]);
    const float c1 = __half2float(kva[tid + 256]);
    float ss = c0 * c0 + c1 * c1;
#pragma unroll
    for (int o = 16; o > 0; o >>= 1) ss += __shfl_xor_sync(0xffffffffu, ss, o);
    __shared__ float red[8];
    if ((tid & 31) == 0) red[tid >> 5] = ss;
    __syncthreads();
    if (tid == 0) {
        float v = 0.f;
#pragma unroll
        for (int i = 0; i < 8; i++) v += red[i];
        red[0] = v;
    }
    __syncthreads();
    const float inv = rsqrtf(red[0] * (1.f / 512.f) + RMS_EPS);
    g_ckvh[(size_t)row * DKVL + tid]       = __float2half_rn(c0 * inv * w[tid]);
    g_ckvh[(size_t)row * DKVL + tid + 256] = __float2half_rn(c1 * inv * w[tid + 256]);

    if (tid < 32) {
        const float fr = expf(-(float)tid * ROPE_LC);
        const float t  = (float)s * fr;
        const float cs = cosf(t), sn = sinf(t);
        const float x1 = __half2float(kva[DKVL + 2 * tid]);
        const float x2 = __half2float(kva[DKVL + 2 * tid + 1]);
        *(__half2*)(g_krh + (size_t)row * DROPE + 2 * tid) =
            __floats2half2_rn(x1 * cs - x2 * sn, x2 * cs + x1 * sn);
    }

    for (int p = tid; p < NH * 32; p += 256) {
        const int h = p >> 5, i = p & 31;
        const float fr = expf(-(float)i * ROPE_LC);
        const float t  = (float)s * fr;
        const float cs = cosf(t), sn = sinf(t);
        __half2* qp = (__half2*)(g_qkvah + (size_t)row * QKVA_N + h * DQKD + DNOPE + 2 * i);
        const __half2 v = *qp;
        const float x1 = __half2float(v.x), x2 = __half2float(v.y);
        *qp = __floats2half2_rn(x1 * cs - x2 * sn, x2 * cs + x1 * sn);
    }
}

// ---------------- fp16 flash attention: BM=256, BN=64, 512 thr ---------------
// 16 warps x 16 rows. Double-buffered K/V (2-stage cp.async). P in registers.
#define QS_STRH 200
#define KS_STRH 200
#define VS_STRH 136
#define QS_HALVES (256 * QS_STRH)        // 51200
#define KS_HALVES (64 * KS_STRH)         // 12800
#define VS_HALVES (64 * VS_STRH)         // 8704
#define KS_OFFH QS_HALVES
#define VS_OFFH (KS_OFFH + 2 * KS_HALVES)
#define ATT_HALVES (VS_OFFH + 2 * VS_HALVES)
#define ATT_BYTES (ATT_HALVES * 2)       // 188416

__global__ void __launch_bounds__(512)
attn_tc()
{
    extern __shared__ __half asm_[];
    const uint32_t sbase = (uint32_t)__cvta_generic_to_shared(asm_);
    const uint32_t sQ = sbase;
    const uint32_t sK = sbase + KS_OFFH * 2;
    const uint32_t sV = sbase + VS_OFFH * 2;

    // LPT scheduling: longest CTAs first
    const int qblk = (S_ / 256 - 1) - blockIdx.x;
    const int h    = blockIdx.y;
    const int b    = blockIdx.z;
    const int tid  = threadIdx.x;
    const int w    = tid >> 5;          // 0..15
    const int lane = tid & 31;
    const int lr   = lane >> 2;
    const int lc   = lane & 3;
    const int g    = lane >> 3;
    const int l8   = lane & 7;
    const int w16  = w * 16;
    const int q0   = qblk * 256;
    const int bS   = b * S_;

    const float scale2 = 0.07216878364870323f * 1.4426950408889634f;

    const uint32_t qB = sQ + (((w16 + l8 + 8 * (g & 1)) * QS_STRH + 8 * (g >> 1)) << 1);
    const uint32_t kB = sK + (((l8 + 8 * (g >> 1)) * KS_STRH + 8 * (g & 1)) << 1);
    const uint32_t vB = sV + (((l8 + 8 * (g & 1)) * VS_STRH + 8 * (g >> 1)) << 1);

    // ---- Q tile: 256 rows x 24 chunks ----
#pragma unroll
    for (int i = 0; i < 12; i++) {
        const int idx = tid + i * 512;
        const int r = idx / 24, c8 = idx % 24;
        cp_async16(sQ + ((r * QS_STRH + c8 * 8) << 1),
                   g_qkvah + (size_t)(bS + q0 + r) * QKVA_N + h * DQKD + c8 * 8, 16);
    }
    CP_COMMIT();

    auto loadKV = [&](int kt, int stage) {
        const int k0 = kt * 64;
        const uint32_t sKs = sK + (uint32_t)stage * KS_HALVES * 2;
        const uint32_t sVs = sV + (uint32_t)stage * VS_HALVES * 2;
#pragma unroll
        for (int i = 0; i < 2; i++) {       // K nope: 64 x 16 chunks
            const int idx = tid + i * 512;
            const int j = idx >> 4, c8 = idx & 15;
            cp_async16(sKs + ((j * KS_STRH + c8 * 8) << 1),
                       g_kvbh + (size_t)(bS + k0 + j) * HKV + h * 256 + c8 * 8, 16);
        }
        {                                   // K rope: 64 x 8 chunks
            const int j = tid >> 3, c8 = tid & 7;
            cp_async16(sKs + ((j * KS_STRH + 128 + c8 * 8) << 1),
                       g_krh + (size_t)(bS + k0 + j) * DROPE + c8 * 8, 16);
        }
#pragma unroll
        for (int i = 0; i < 2; i++) {       // V: 64 x 16 chunks
            const int idx = tid + i * 512;
            const int j = idx >> 4, c8 = idx & 15;
            cp_async16(sVs + ((j * VS_STRH + c8 * 8) << 1),
                       g_kvbh + (size_t)(bS + k0 + j) * HKV + h * 256 + 128 + c8 * 8, 16);
        }
        CP_COMMIT();
    };

    float oacc[16][4];
#pragma unroll
    for (int i = 0; i < 16; i++)
#pragma unroll
        for (int j = 0; j < 4; j++) oacc[i][j] = 0.f;
    float m0v = -1e30f, m1v = -1e30f, l0 = 0.f, l1 = 0.f;

    const int row0g = q0 + w16 + lr;
    const int row1g = row0g + 8;
    const int lastNeeded = q0 + w16 + 15;

    const int ktMax = 4 * qblk + 3;
    loadKV(0, 0);

    for (int kt = 0; kt <= ktMax; kt++) {
        const int k0 = kt * 64;
        const int stage = kt & 1;
        if (kt < ktMax) { loadKV(kt + 1, stage ^ 1); CP_WAIT(1); }
        else            { CP_WAIT(0); }
        __syncthreads();

        if (k0 <= lastNeeded) {
            const uint32_t kBs = kB + (uint32_t)stage * KS_HALVES * 2;
            const uint32_t vBs = vB + (uint32_t)stage * VS_HALVES * 2;

            // ---- S = Q @ K^T ----
            float sacc[8][4];
#pragma unroll
            for (int i = 0; i < 8; i++)
#pragma unroll
                for (int j = 0; j < 4; j++) sacc[i][j] = 0.f;

#pragma unroll
            for (int ks = 0; ks < 12; ks++) {
                unsigned a[4];
                ldsm4(a, qB + ks * 32);
#pragma unroll
                for (int p = 0; p < 4; p++) {
                    unsigned bb[4];
                    ldsm4(bb, kBs + ks * 32 + p * (16 * KS_STRH * 2));
                    mma16(sacc[2 * p],     a, bb[0], bb[1]);
                    mma16(sacc[2 * p + 1], a, bb[2], bb[3]);
                }
            }

            // ---- mask + scale (log2 domain), row max ----
            const bool domask = (k0 + 63 > q0 + w16);
            float mt0 = -1e30f, mt1 = -1e30f;
#pragma unroll
            for (int nt = 0; nt < 8; nt++) {
                const int jb = k0 + nt * 8 + 2 * lc;
#pragma unroll
                for (int c = 0; c < 4; c++) {
                    float s = sacc[nt][c] * scale2;
                    const int jg = jb + (c & 1);
                    const int rg = (c < 2) ? row0g : row1g;
                    if (domask && jg > rg) s = -1e30f;
                    sacc[nt][c] = s;
                    if (c < 2) mt0 = fmaxf(mt0, s); else mt1 = fmaxf(mt1, s);
                }
            }
            mt0 = fmaxf(mt0, __shfl_xor_sync(0xffffffffu, mt0, 1));
            mt0 = fmaxf(mt0, __shfl_xor_sync(0xffffffffu, mt0, 2));
            mt1 = fmaxf(mt1, __shfl_xor_sync(0xffffffffu, mt1, 1));
            mt1 = fmaxf(mt1, __shfl_xor_sync(0xffffffffu, mt1, 2));

            const float mn0 = fmaxf(m0v, mt0);
            const float mn1 = fmaxf(m1v, mt1);
            const float al0 = exp2f(m0v - mn0);
            const float al1 = exp2f(m1v - mn1);
            m0v = mn0; m1v = mn1;

            // ---- P = exp2(S - m) in registers; row sums ----
            float rs0 = 0.f, rs1 = 0.f;
#pragma unroll
            for (int nt = 0; nt < 8; nt++) {
                sacc[nt][0] = exp2f(sacc[nt][0] - mn0);
                sacc[nt][1] = exp2f(sacc[nt][1] - mn0);
                sacc[nt][2] = exp2f(sacc[nt][2] - mn1);
                sacc[nt][3] = exp2f(sacc[nt][3] - mn1);
                rs0 += sacc[nt][0] + sacc[nt][1];
                rs1 += sacc[nt][2] + sacc[nt][3];
            }
            rs0 += __shfl_xor_sync(0xffffffffu, rs0, 1);
            rs0 += __shfl_xor_sync(0xffffffffu, rs0, 2);
            rs1 += __shfl_xor_sync(0xffffffffu, rs1, 1);
            rs1 += __shfl_xor_sync(0xffffffffu, rs1, 2);
            l0 = l0 * al0 + rs0;
            l1 = l1 * al1 + rs1;

            // ---- rescale O ----
#pragma unroll
            for (int nt = 0; nt < 16; nt++) {
                oacc[nt][0] *= al0; oacc[nt][1] *= al0;
                oacc[nt][2] *= al1; oacc[nt][3] *= al1;
            }

            // ---- pack P C-frags into A-frags (register only) ----
            unsigned pa[4][4];
#pragma unroll
            for (int ks = 0; ks < 4; ks++) {
                pa[ks][0] = packh2(sacc[2 * ks][0],     sacc[2 * ks][1]);
                pa[ks][1] = packh2(sacc[2 * ks][2],     sacc[2 * ks][3]);
                pa[ks][2] = packh2(sacc[2 * ks + 1][0], sacc[2 * ks + 1][1]);
                pa[ks][3] = packh2(sacc[2 * ks + 1][2], sacc[2 * ks + 1][3]);
            }

            // ---- O += P @ V : V via ldmatrix.trans ----
#pragma unroll
            for (int ks = 0; ks < 4; ks++) {
#pragma unroll
                for (int p = 0; p < 8; p++) {
                    unsigned bb[4];
                    ldsm4t(bb, vBs + ks * (16 * VS_STRH * 2) + p * 32);
                    mma16(oacc[2 * p],     pa[ks], bb[0], bb[1]);
                    mma16(oacc[2 * p + 1], pa[ks], bb[2], bb[3]);
                }
            }
        }
        __syncthreads();
    }

    const float inv0 = 1.f / l0;
    const float inv1 = 1.f / l1;
#pragma unroll
    for (int nt = 0; nt < 16; nt++) {
        const int col = h * DV + nt * 8 + 2 * lc;
        *(__half2*)(g_atth + (size_t)(bS + row0g) * (NH * DV) + col) =
            __floats2half2_rn(oacc[nt][0] * inv0, oacc[nt][1] * inv0);
        *(__half2*)(g_atth + (size_t)(bS + row1g) * (NH * DV) + col) =
            __floats2half2_rn(oacc[nt][2] * inv1, oacc[nt][3] * inv1);
    }
}

// ---------------- launch ----------------
extern "C" void kernel_launch(void* const* d_in, const int* in_sizes, int n_in,
                              void* d_out, int out_size)
{
    const float* x     = (const float*)d_in[0];
    const float* Wq    = (const float*)d_in[1];
    const float* Wkv_a = (const float*)d_in[2];
    const float* knw   = (const float*)d_in[3];
    const float* Wkv_b = (const float*)d_in[4];
    const float* Wo    = (const float*)d_in[5];
    float* out = (float*)d_out;

    static __half *p_qkva, *p_ckvh, *p_kvbh, *p_atth;
    static __half *p_xh, *p_wqa, *p_wkvbTh, *p_woTh;
    static bool init = false;
    if (!init) {
        cudaGetSymbolAddress((void**)&p_qkva,   g_qkvah);
        cudaGetSymbolAddress((void**)&p_ckvh,   g_ckvh);
        cudaGetSymbolAddress((void**)&p_kvbh,   g_kvbh);
        cudaGetSymbolAddress((void**)&p_atth,   g_atth);
        cudaGetSymbolAddress((void**)&p_xh,     g_xh);
        cudaGetSymbolAddress((void**)&p_wqa,    g_wqaTh);
        cudaGetSymbolAddress((void**)&p_wkvbTh, g_wkvbTh);
        cudaGetSymbolAddress((void**)&p_woTh,   g_woTh);
        cudaFuncSetAttribute(attn_tc,
                             cudaFuncAttributeMaxDynamicSharedMemorySize, ATT_BYTES);
        cudaFuncSetAttribute(gemm_h,
                             cudaFuncAttributeMaxDynamicSharedMemorySize, GEMM_SMEM_BYTES);
        init = true;
    }

    {
        const int n4 = BS * DM / 4;
        f2h_kernel<<<(n4 + 255) / 256, 256>>>((const float4*)x, (__half2*)p_xh, n4);
    }
    const dim3 tb(32, 8);
    trTh_kernel<<<dim3(HQ / 32, DM / 32), tb>>>(Wq, p_wqa, DM, HQ);
    trTh_kernel<<<dim3(KVA_N / 32, DM / 32), tb>>>(Wkv_a, p_wqa + (size_t)HQ * DM, DM, KVA_N);
    trTh_kernel<<<dim3(HKV / 32, DKVL / 32), tb>>>(Wkv_b, p_wkvbTh, DKVL, HKV);
    trTh_kernel<<<dim3(DM / 32, DM / 32), tb>>>(Wo, p_woTh, DM, DM);

    const dim3 blk(256);
    gemm_h<<<dim3((QKVA_N + 127) / 128, BS / 128), blk, GEMM_SMEM_BYTES>>>(
        p_xh, p_wqa, p_qkva, BS, QKVA_N, DM, 1);
    prep_kernel<<<BS, 256>>>(knw);
    gemm_h<<<dim3(HKV / 128, BS / 128), blk, GEMM_SMEM_BYTES>>>(
        p_ckvh, p_wkvbTh, p_kvbh, BS, HKV, DKVL, 1);
    attn_tc<<<dim3(S_ / 256, NH, B_), 512, ATT_BYTES>>>();
    gemm_h<<<dim3(DM / 128, BS / 128), blk, GEMM_SMEM_BYTES>>>(
        p_atth, p_woTh, out, BS, DM, DM, 0);
}

// round 12
// speedup vs baseline: 1.0651x; 1.0038x over previous
#include <cuda_runtime.h>
#include <cuda_fp16.h>
#include <math.h>
#include <stdint.h>

// ---------------- problem dims ----------------
#define B_      2
#define S_      2048
#define DM      2048
#define NH      16
#define DNOPE   128
#define DROPE   64
#define DQKD    192
#define DKVL    512
#define DV      128
#define BS      (B_*S_)          // 4096
#define HQ      (NH*DQKD)        // 3072
#define HKV     (NH*(DNOPE+DV))  // 4096
#define KVA_N   (DKVL+DROPE)     // 576
#define QKVA_N  (HQ+KVA_N)       // 3648
#define RMS_EPS 1.1920928955078125e-07f
#define ROPE_LC 0.28782313662425572f   // ln(10000)/32

// ---------------- scratch (fp16 pipeline) ----------------
__device__ alignas(16) __half g_qkvah[BS*QKVA_N];  // [q (3072) | kva (576)]
__device__ alignas(16) __half g_ckvh[BS*DKVL];
__device__ alignas(16) __half g_krh [BS*DROPE];
__device__ alignas(16) __half g_kvbh[BS*HKV];
__device__ alignas(16) __half g_atth[BS*(NH*DV)];
__device__ alignas(16) __half g_xh  [BS*DM];
__device__ alignas(16) __half g_wqaTh[QKVA_N*DM];  // [WqT | WkvaT] k-major
__device__ alignas(16) __half g_wkvbTh[HKV*DKVL];
__device__ alignas(16) __half g_woTh [DM*NH*DV];

// ---------------- helpers ----------------
__device__ __forceinline__ void mma16(float* c, const unsigned* a,
                                      unsigned b0, unsigned b1) {
    asm volatile(
        "mma.sync.aligned.m16n8k16.row.col.f32.f16.f16.f32 "
        "{%0,%1,%2,%3},{%4,%5,%6,%7},{%8,%9},{%0,%1,%2,%3};\n"
        : "+f"(c[0]), "+f"(c[1]), "+f"(c[2]), "+f"(c[3])
        : "r"(a[0]), "r"(a[1]), "r"(a[2]), "r"(a[3]), "r"(b0), "r"(b1));
}

__device__ __forceinline__ void ldsm4(unsigned* r, uint32_t addr) {
    asm volatile("ldmatrix.sync.aligned.m8n8.x4.shared.b16 {%0,%1,%2,%3}, [%4];"
                 : "=r"(r[0]), "=r"(r[1]), "=r"(r[2]), "=r"(r[3]) : "r"(addr));
}
__device__ __forceinline__ void ldsm4t(unsigned* r, uint32_t addr) {
    asm volatile("ldmatrix.sync.aligned.m8n8.x4.trans.shared.b16 {%0,%1,%2,%3}, [%4];"
                 : "=r"(r[0]), "=r"(r[1]), "=r"(r[2]), "=r"(r[3]) : "r"(addr));
}

__device__ __forceinline__ void cp_async16(uint32_t dst, const void* src, int srcBytes) {
    asm volatile("cp.async.cg.shared.global [%0], [%1], 16, %2;\n"
                 :: "r"(dst), "l"(src), "r"(srcBytes));
}
#define CP_COMMIT() asm volatile("cp.async.commit_group;\n" ::: "memory")
#define CP_WAIT(n)  asm volatile("cp.async.wait_group %0;\n" :: "n"(n) : "memory")

__device__ __forceinline__ unsigned packh2(float a, float b) {
    const __half2 h = __floats2half2_rn(a, b);
    return *(const unsigned*)&h;
}

// ---------------- fused conversion: f2h(x) + 4 transposed weights ------------
#define CV_XB   2048                // x: 2M float4, 4 per thread, 256 thr
#define CV_WQ   (96 * 64)           // 6144
#define CV_WKVA (18 * 64)           // 1152
#define CV_WKVB (128 * 16)          // 2048
#define CV_WO   (64 * 64)           // 4096
#define CV_BLOCKS (CV_XB + CV_WQ + CV_WKVA + CV_WKVB + CV_WO)  // 15488

__global__ void convert_all(const float* __restrict__ x,
                            const float* __restrict__ Wq,
                            const float* __restrict__ Wkv_a,
                            const float* __restrict__ Wkv_b,
                            const float* __restrict__ Wo)
{
    int bid = blockIdx.x;
    const int tid = threadIdx.x;

    if (bid < CV_XB) {
        const float4* in = (const float4*)x;
        __half2* outp = (__half2*)g_xh;
        const int base = bid * 1024 + tid;
#pragma unroll
        for (int i = 0; i < 4; i++) {
            const int idx = base + i * 256;
            const float4 v = in[idx];
            outp[2 * idx]     = __floats2half2_rn(v.x, v.y);
            outp[2 * idx + 1] = __floats2half2_rn(v.z, v.w);
        }
        return;
    }
    bid -= CV_XB;

    const float* in;
    __half* outp;
    int R, C, tX, tY;
    if (bid < CV_WQ) {
        in = Wq; outp = g_wqaTh; R = DM; C = HQ;
        tX = bid % 96; tY = bid / 96;
    } else if ((bid -= CV_WQ) < CV_WKVA) {
        in = Wkv_a; outp = g_wqaTh + (size_t)HQ * DM; R = DM; C = KVA_N;
        tX = bid % 18; tY = bid / 18;
    } else if ((bid -= CV_WKVA) < CV_WKVB) {
        in = Wkv_b; outp = g_wkvbTh; R = DKVL; C = HKV;
        tX = bid % 128; tY = bid / 128;
    } else {
        bid -= CV_WKVB;
        in = Wo; outp = g_woTh; R = DM; C = DM;
        tX = bid % 64; tY = bid / 64;
    }

    __shared__ float t[32][33];
    const int lx = tid & 31, ly = tid >> 5;
    const int c0 = tX * 32, r0 = tY * 32;
#pragma unroll
    for (int i = 0; i < 4; i++)
        t[ly + i * 8][lx] = in[(size_t)(r0 + ly + i * 8) * C + c0 + lx];
    __syncthreads();
#pragma unroll
    for (int i = 0; i < 4; i++)
        outp[(size_t)(c0 + ly + i * 8) * R + r0 + lx] = __float2half_rn(t[lx][ly + i * 8]);
}

// ---------------- fp16 GEMM: C[M,N] = A[M,K] @ Bt[N,K]^T --------------------
// 128x128x64 tile, 256 thr (8 warps: wm 0..3 x wn 0..1), warp 32x64.
// 2-stage cp.async -> 73.7KB smem -> 2 CTAs/SM.
#define GASTRH   72
#define GTILE_B  (128 * GASTRH * 2)     // 18432
#define GSTAGE_B (2 * GTILE_B)
#define GEMM_SMEM_BYTES (2 * GSTAGE_B)  // 73728

__global__ void __launch_bounds__(256, 2)
gemm_h(const __half* __restrict__ A, const __half* __restrict__ Bt,
       void* __restrict__ C, int M, int N, int K, int outHalf)
{
    extern __shared__ __half hsm[];
    const uint32_t sb = (uint32_t)__cvta_generic_to_shared(hsm);

    const int tid  = threadIdx.x;
    const int wid  = tid >> 5;
    const int lane = tid & 31;
    const int lr   = lane >> 2;
    const int lc   = lane & 3;
    const int g    = lane >> 3;
    const int l8   = lane & 7;
    const int wm   = wid & 3;
    const int wn   = wid >> 2;
    const int m0   = blockIdx.y * 128;
    const int n0   = blockIdx.x * 128;

    const uint32_t aBase = sb + (((wm * 32 + l8 + 8 * (g & 1)) * GASTRH + 8 * (g >> 1)) << 1);
    const uint32_t bBase = sb + GTILE_B +
                           (((wn * 64 + l8 + 8 * (g >> 1)) * GASTRH + 8 * (g & 1)) << 1);

    float acc[2][8][4];
#pragma unroll
    for (int i = 0; i < 2; i++)
#pragma unroll
        for (int j = 0; j < 8; j++)
#pragma unroll
            for (int k = 0; k < 4; k++) acc[i][j][k] = 0.f;

    auto loadTile = [&](int stage, int kt) {
        const uint32_t s0 = sb + (uint32_t)stage * GSTAGE_B;
        const int kb = kt * 64;
#pragma unroll
        for (int i = 0; i < 4; i++) {
            const int idx = tid + i * 256;
            const int row = idx >> 3, c8 = idx & 7;
            cp_async16(s0 + ((row * GASTRH + c8 * 8) << 1),
                       A + (size_t)(m0 + row) * K + kb + c8 * 8, 16);
        }
#pragma unroll
        for (int i = 0; i < 4; i++) {
            const int idx = tid + i * 256;
            const int n = idx >> 3, c8 = idx & 7;
            const int ng = n0 + n;
            const int ngc = ng < N ? ng : 0;
            cp_async16(s0 + GTILE_B + ((n * GASTRH + c8 * 8) << 1),
                       Bt + (size_t)ngc * K + kb + c8 * 8, ng < N ? 16 : 0);
        }
        CP_COMMIT();
    };

    const int T = K >> 6;
    loadTile(0, 0);
    if (T > 1) loadTile(1, 1);

    for (int it = 0; it < T; it++) {
        if (it + 1 < T) { CP_WAIT(1); } else { CP_WAIT(0); }
        __syncthreads();

        const uint32_t st = (uint32_t)(it & 1) * GSTAGE_B;
#pragma unroll
        for (int ks = 0; ks < 4; ks++) {
            unsigned a[2][4];
            ldsm4(a[0], aBase + st + ks * 32);
            ldsm4(a[1], aBase + st + ks * 32 + 16 * GASTRH * 2);
            unsigned b[8][2];
#pragma unroll
            for (int p = 0; p < 4; p++) {
                unsigned bb[4];
                ldsm4(bb, bBase + st + ks * 32 + p * (16 * GASTRH * 2));
                b[2 * p][0] = bb[0]; b[2 * p][1] = bb[1];
                b[2 * p + 1][0] = bb[2]; b[2 * p + 1][1] = bb[3];
            }
#pragma unroll
            for (int nt = 0; nt < 8; nt++) {
                mma16(acc[0][nt], a[0], b[nt][0], b[nt][1]);
                mma16(acc[1][nt], a[1], b[nt][0], b[nt][1]);
            }
        }
        if (it + 2 < T) {
            __syncthreads();
            loadTile(it & 1, it + 2);
        }
    }

#pragma unroll
    for (int mt = 0; mt < 2; mt++)
#pragma unroll
        for (int nt = 0; nt < 8; nt++) {
            const int row = m0 + wm * 32 + mt * 16 + lr;
            const int col = n0 + wn * 64 + nt * 8 + 2 * lc;
            if (col < N) {
                if (outHalf) {
                    *(__half2*)((__half*)C + (size_t)row * N + col) =
                        __floats2half2_rn(acc[mt][nt][0], acc[mt][nt][1]);
                    *(__half2*)((__half*)C + (size_t)(row + 8) * N + col) =
                        __floats2half2_rn(acc[mt][nt][2], acc[mt][nt][3]);
                } else {
                    *(float2*)((float*)C + (size_t)row * N + col) =
                        make_float2(acc[mt][nt][0], acc[mt][nt][1]);
                    *(float2*)((float*)C + (size_t)(row + 8) * N + col) =
                        make_float2(acc[mt][nt][2], acc[mt][nt][3]);
                }
            }
        }
}

// ---------------- prep: RMSNorm(c_kv), RoPE(k_rope), RoPE(q) -----------------
__global__ void prep_kernel(const float* __restrict__ w)
{
    const int row = blockIdx.x;
    const int s   = row % S_;
    const int tid = threadIdx.x;
    const __half* kva = g_qkvah + (size_t)row * QKVA_N + HQ;

    const float c0 = __half2float(kva[tid]);
    const float c1 = __half2float(kva[tid + 256]);
    float ss = c0 * c0 + c1 * c1;
#pragma unroll
    for (int o = 16; o > 0; o >>= 1) ss += __shfl_xor_sync(0xffffffffu, ss, o);
    __shared__ float red[8];
    if ((tid & 31) == 0) red[tid >> 5] = ss;
    __syncthreads();
    if (tid == 0) {
        float v = 0.f;
#pragma unroll
        for (int i = 0; i < 8; i++) v += red[i];
        red[0] = v;
    }
    __syncthreads();
    const float inv = rsqrtf(red[0] * (1.f / 512.f) + RMS_EPS);
    g_ckvh[(size_t)row * DKVL + tid]       = __float2half_rn(c0 * inv * w[tid]);
    g_ckvh[(size_t)row * DKVL + tid + 256] = __float2half_rn(c1 * inv * w[tid + 256]);

    if (tid < 32) {
        const float fr = expf(-(float)tid * ROPE_LC);
        const float t  = (float)s * fr;
        const float cs = cosf(t), sn = sinf(t);
        const float x1 = __half2float(kva[DKVL + 2 * tid]);
        const float x2 = __half2float(kva[DKVL + 2 * tid + 1]);
        *(__half2*)(g_krh + (size_t)row * DROPE + 2 * tid) =
            __floats2half2_rn(x1 * cs - x2 * sn, x2 * cs + x1 * sn);
    }

    for (int p = tid; p < NH * 32; p += 256) {
        const int h = p >> 5, i = p & 31;
        const float fr = expf(-(float)i * ROPE_LC);
        const float t  = (float)s * fr;
        const float cs = cosf(t), sn = sinf(t);
        __half2* qp = (__half2*)(g_qkvah + (size_t)row * QKVA_N + h * DQKD + DNOPE + 2 * i);
        const __half2 v = *qp;
        const float x1 = __half2float(v.x), x2 = __half2float(v.y);
        *qp = __floats2half2_rn(x1 * cs - x2 * sn, x2 * cs + x1 * sn);
    }
}

// ---------------- fp16 flash attention: BM=256, BN=64, 512 thr ---------------
// Single __syncthreads per kt; rescale skipped (exact no-op) when warp-uniform.
#define QS_STRH 200
#define KS_STRH 200
#define VS_STRH 136
#define QS_HALVES (256 * QS_STRH)        // 51200
#define KS_HALVES (64 * KS_STRH)         // 12800
#define VS_HALVES (64 * VS_STRH)         // 8704
#define KS_OFFH QS_HALVES
#define VS_OFFH (KS_OFFH + 2 * KS_HALVES)
#define ATT_HALVES (VS_OFFH + 2 * VS_HALVES)
#define ATT_BYTES (ATT_HALVES * 2)       // 188416

__global__ void __launch_bounds__(512)
attn_tc()
{
    extern __shared__ __half asm_[];
    const uint32_t sbase = (uint32_t)__cvta_generic_to_shared(asm_);
    const uint32_t sQ = sbase;
    const uint32_t sK = sbase + KS_OFFH * 2;
    const uint32_t sV = sbase + VS_OFFH * 2;

    const int qblk = (S_ / 256 - 1) - blockIdx.x;   // LPT
    const int h    = blockIdx.y;
    const int b    = blockIdx.z;
    const int tid  = threadIdx.x;
    const int w    = tid >> 5;
    const int lane = tid & 31;
    const int lr   = lane >> 2;
    const int lc   = lane & 3;
    const int g    = lane >> 3;
    const int l8   = lane & 7;
    const int w16  = w * 16;
    const int q0   = qblk * 256;
    const int bS   = b * S_;

    const float scale2 = 0.07216878364870323f * 1.4426950408889634f;

    const uint32_t qB = sQ + (((w16 + l8 + 8 * (g & 1)) * QS_STRH + 8 * (g >> 1)) << 1);
    const uint32_t kB = sK + (((l8 + 8 * (g >> 1)) * KS_STRH + 8 * (g & 1)) << 1);
    const uint32_t vB = sV + (((l8 + 8 * (g & 1)) * VS_STRH + 8 * (g >> 1)) << 1);

    // ---- Q tile: 256 rows x 24 chunks ----
#pragma unroll
    for (int i = 0; i < 12; i++) {
        const int idx = tid + i * 512;
        const int r = idx / 24, c8 = idx % 24;
        cp_async16(sQ + ((r * QS_STRH + c8 * 8) << 1),
                   g_qkvah + (size_t)(bS + q0 + r) * QKVA_N + h * DQKD + c8 * 8, 16);
    }
    CP_COMMIT();

    auto loadKV = [&](int kt, int stage) {
        const int k0 = kt * 64;
        const uint32_t sKs = sK + (uint32_t)stage * KS_HALVES * 2;
        const uint32_t sVs = sV + (uint32_t)stage * VS_HALVES * 2;
#pragma unroll
        for (int i = 0; i < 2; i++) {
            const int idx = tid + i * 512;
            const int j = idx >> 4, c8 = idx & 15;
            cp_async16(sKs + ((j * KS_STRH + c8 * 8) << 1),
                       g_kvbh + (size_t)(bS + k0 + j) * HKV + h * 256 + c8 * 8, 16);
        }
        {
            const int j = tid >> 3, c8 = tid & 7;
            cp_async16(sKs + ((j * KS_STRH + 128 + c8 * 8) << 1),
                       g_krh + (size_t)(bS + k0 + j) * DROPE + c8 * 8, 16);
        }
#pragma unroll
        for (int i = 0; i < 2; i++) {
            const int idx = tid + i * 512;
            const int j = idx >> 4, c8 = idx & 15;
            cp_async16(sVs + ((j * VS_STRH + c8 * 8) << 1),
                       g_kvbh + (size_t)(bS + k0 + j) * HKV + h * 256 + 128 + c8 * 8, 16);
        }
        CP_COMMIT();
    };

    float oacc[16][4];
#pragma unroll
    for (int i = 0; i < 16; i++)
#pragma unroll
        for (int j = 0; j < 4; j++) oacc[i][j] = 0.f;
    float m0v = -1e30f, m1v = -1e30f, l0 = 0.f, l1 = 0.f;

    const int row0g = q0 + w16 + lr;
    const int row1g = row0g + 8;
    const int lastNeeded = q0 + w16 + 15;

    const int ktMax = 4 * qblk + 3;
    loadKV(0, 0);

    for (int kt = 0; kt <= ktMax; kt++) {
        const int k0 = kt * 64;
        const int stage = kt & 1;

        CP_WAIT(0);
        __syncthreads();
        // issue next tile AFTER the barrier: all warps are past their reads of
        // stage^1 (consumed in iteration kt-1), so the overwrite is safe and the
        // load overlaps this iteration's compute. One barrier per kt.
        if (kt < ktMax) loadKV(kt + 1, stage ^ 1);

        if (k0 <= lastNeeded) {
            const uint32_t kBs = kB + (uint32_t)stage * KS_HALVES * 2;
            const uint32_t vBs = vB + (uint32_t)stage * VS_HALVES * 2;

            // ---- S = Q @ K^T ----
            float sacc[8][4];
#pragma unroll
            for (int i = 0; i < 8; i++)
#pragma unroll
                for (int j = 0; j < 4; j++) sacc[i][j] = 0.f;

#pragma unroll
            for (int ks = 0; ks < 12; ks++) {
                unsigned a[4];
                ldsm4(a, qB + ks * 32);
#pragma unroll
                for (int p = 0; p < 4; p++) {
                    unsigned bb[4];
                    ldsm4(bb, kBs + ks * 32 + p * (16 * KS_STRH * 2));
                    mma16(sacc[2 * p],     a, bb[0], bb[1]);
                    mma16(sacc[2 * p + 1], a, bb[2], bb[3]);
                }
            }

            // ---- mask + scale (log2 domain), row max ----
            const bool domask = (k0 + 63 > q0 + w16);
            float mt0 = -1e30f, mt1 = -1e30f;
#pragma unroll
            for (int nt = 0; nt < 8; nt++) {
                const int jb = k0 + nt * 8 + 2 * lc;
#pragma unroll
                for (int c = 0; c < 4; c++) {
                    float s = sacc[nt][c] * scale2;
                    const int jg = jb + (c & 1);
                    const int rg = (c < 2) ? row0g : row1g;
                    if (domask && jg > rg) s = -1e30f;
                    sacc[nt][c] = s;
                    if (c < 2) mt0 = fmaxf(mt0, s); else mt1 = fmaxf(mt1, s);
                }
            }
            mt0 = fmaxf(mt0, __shfl_xor_sync(0xffffffffu, mt0, 1));
            mt0 = fmaxf(mt0, __shfl_xor_sync(0xffffffffu, mt0, 2));
            mt1 = fmaxf(mt1, __shfl_xor_sync(0xffffffffu, mt1, 1));
            mt1 = fmaxf(mt1, __shfl_xor_sync(0xffffffffu, mt1, 2));

            const float mn0 = fmaxf(m0v, mt0);
            const float mn1 = fmaxf(m1v, mt1);
            // warp-uniform skip: when no row got a new max, al == 1.0 exactly
            const bool doResc =
                !__all_sync(0xffffffffu, (mn0 == m0v) && (mn1 == m1v));
            const float al0 = exp2f(m0v - mn0);
            const float al1 = exp2f(m1v - mn1);
            m0v = mn0; m1v = mn1;

            // ---- P = exp2(S - m) in registers; row sums ----
            float rs0 = 0.f, rs1 = 0.f;
#pragma unroll
            for (int nt = 0; nt < 8; nt++) {
                sacc[nt][0] = exp2f(sacc[nt][0] - mn0);
                sacc[nt][1] = exp2f(sacc[nt][1] - mn0);
                sacc[nt][2] = exp2f(sacc[nt][2] - mn1);
                sacc[nt][3] = exp2f(sacc[nt][3] - mn1);
                rs0 += sacc[nt][0] + sacc[nt][1];
                rs1 += sacc[nt][2] + sacc[nt][3];
            }
            rs0 += __shfl_xor_sync(0xffffffffu, rs0, 1);
            rs0 += __shfl_xor_sync(0xffffffffu, rs0, 2);
            rs1 += __shfl_xor_sync(0xffffffffu, rs1, 1);
            rs1 += __shfl_xor_sync(0xffffffffu, rs1, 2);
            l0 = l0 * al0 + rs0;
            l1 = l1 * al1 + rs1;

            // ---- rescale O (exact no-op when skipped) ----
            if (doResc) {
#pragma unroll
                for (int nt = 0; nt < 16; nt++) {
                    oacc[nt][0] *= al0; oacc[nt][1] *= al0;
                    oacc[nt][2] *= al1; oacc[nt][3] *= al1;
                }
            }

            // ---- pack P C-frags into A-frags (register only) ----
            unsigned pa[4][4];
#pragma unroll
            for (int ks = 0; ks < 4; ks++) {
                pa[ks][0] = packh2(sacc[2 * ks][0],     sacc[2 * ks][1]);
                pa[ks][1] = packh2(sacc[2 * ks][2],     sacc[2 * ks][3]);
                pa[ks][2] = packh2(sacc[2 * ks + 1][0], sacc[2 * ks + 1][1]);
                pa[ks][3] = packh2(sacc[2 * ks + 1][2], sacc[2 * ks + 1][3]);
            }

            // ---- O += P @ V : V via ldmatrix.trans ----
#pragma unroll
            for (int ks = 0; ks < 4; ks++) {
#pragma unroll
                for (int p = 0; p < 8; p++) {
                    unsigned bb[4];
                    ldsm4t(bb, vBs + ks * (16 * VS_STRH * 2) + p * 32);
                    mma16(oacc[2 * p],     pa[ks], bb[0], bb[1]);
                    mma16(oacc[2 * p + 1], pa[ks], bb[2], bb[3]);
                }
            }
        }
    }

    const float inv0 = 1.f / l0;
    const float inv1 = 1.f / l1;
#pragma unroll
    for (int nt = 0; nt < 16; nt++) {
        const int col = h * DV + nt * 8 + 2 * lc;
        *(__half2*)(g_atth + (size_t)(bS + row0g) * (NH * DV) + col) =
            __floats2half2_rn(oacc[nt][0] * inv0, oacc[nt][1] * inv0);
        *(__half2*)(g_atth + (size_t)(bS + row1g) * (NH * DV) + col) =
            __floats2half2_rn(oacc[nt][2] * inv1, oacc[nt][3] * inv1);
    }
}

// ---------------- launch ----------------
extern "C" void kernel_launch(void* const* d_in, const int* in_sizes, int n_in,
                              void* d_out, int out_size)
{
    const float* x     = (const float*)d_in[0];
    const float* Wq    = (const float*)d_in[1];
    const float* Wkv_a = (const float*)d_in[2];
    const float* knw   = (const float*)d_in[3];
    const float* Wkv_b = (const float*)d_in[4];
    const float* Wo    = (const float*)d_in[5];
    float* out = (float*)d_out;

    static __half *p_qkva, *p_ckvh, *p_kvbh, *p_atth;
    static __half *p_xh, *p_wqa, *p_wkvbTh, *p_woTh;
    static bool init = false;
    if (!init) {
        cudaGetSymbolAddress((void**)&p_qkva,   g_qkvah);
        cudaGetSymbolAddress((void**)&p_ckvh,   g_ckvh);
        cudaGetSymbolAddress((void**)&p_kvbh,   g_kvbh);
        cudaGetSymbolAddress((void**)&p_atth,   g_atth);
        cudaGetSymbolAddress((void**)&p_xh,     g_xh);
        cudaGetSymbolAddress((void**)&p_wqa,    g_wqaTh);
        cudaGetSymbolAddress((void**)&p_wkvbTh, g_wkvbTh);
        cudaGetSymbolAddress((void**)&p_woTh,   g_woTh);
        cudaFuncSetAttribute(attn_tc,
                             cudaFuncAttributeMaxDynamicSharedMemorySize, ATT_BYTES);
        cudaFuncSetAttribute(gemm_h,
                             cudaFuncAttributeMaxDynamicSharedMemorySize, GEMM_SMEM_BYTES);
        init = true;
    }

    convert_all<<<CV_BLOCKS, 256>>>(x, Wq, Wkv_a, Wkv_b, Wo);

    const dim3 blk(256);
    gemm_h<<<dim3((QKVA_N + 127) / 128, BS / 128), blk, GEMM_SMEM_BYTES>>>(
        p_xh, p_wqa, p_qkva, BS, QKVA_N, DM, 1);
    prep_kernel<<<BS, 256>>>(knw);
    gemm_h<<<dim3(HKV / 128, BS / 128), blk, GEMM_SMEM_BYTES>>>(
        p_ckvh, p_wkvbTh, p_kvbh, BS, HKV, DKVL, 1);
    attn_tc<<<dim3(S_ / 256, NH, B_), 512, ATT_BYTES>>>();
    gemm_h<<<dim3(DM / 128, BS / 128), blk, GEMM_SMEM_BYTES>>>(
        p_atth, p_woTh, out, BS, DM, DM, 0);
}